// round 9
// baseline (speedup 1.0000x reference)
#include <cuda_runtime.h>
#include <cuda_bf16.h>
#include <math.h>

// Problem dims
#define T_TOK 2048   // B*S
#define DIM   768
#define NH    12
#define NL    4
#define NE    8
#define FF    3072
#define VOC   32000
#define SEQ   512
#define BAT   4
#define HD    64

// ---------------- static scratch (allocation-free rule) ----------------
__device__ float g_x   [T_TOK * DIM];
__device__ float g_emb [T_TOK * DIM];
__device__ float g_tmp [T_TOK * DIM];
__device__ float g_attn[T_TOK * DIM];
__device__ float g_qkv [T_TOK * 3 * DIM];
__device__ float g_scores[(size_t)BAT * NH * SEQ * SEQ];
__device__ float g_h  [(size_t)NE * T_TOK * FF];
__device__ float g_eo [(size_t)NE * T_TOK * DIM];
__device__ float g_gates[T_TOK * NE];

// ---------------- f32x2 helpers (FFMA2 path, 2x fp32 throughput) -------
__device__ __forceinline__ void fma2(unsigned long long &acc,
                                     unsigned long long a,
                                     unsigned long long b) {
    asm("fma.rn.f32x2 %0, %1, %2, %0;" : "+l"(acc) : "l"(a), "l"(b));
}
__device__ __forceinline__ unsigned long long bcast2(float v) {
    unsigned long long r; unsigned int u = __float_as_uint(v);
    asm("mov.b64 %0, {%1, %1};" : "=l"(r) : "r"(u));
    return r;
}
__device__ __forceinline__ float2 unpack2(unsigned long long v) {
    unsigned int lo, hi;
    asm("mov.b64 {%0, %1}, %2;" : "=r"(lo), "=r"(hi) : "l"(v));
    return make_float2(__uint_as_float(lo), __uint_as_float(hi));
}

// ---------------- generic GEMM: C[m,n] = f(alpha*sum_k A[m,k]*B[n,k] + beta*bias[n])
//                                  + c1*add1[m,n] + c2*add2[m,n]
// If qsp != null: c1 = 1-*qsp, c2 = *qsp  (quantum mix, read on device)
// f = exact GELU if do_gelu. Batched via blockIdx.z with element strides.
// Requires M%128==0, N%128==0, K%8==0 (true for every call here).
__global__ __launch_bounds__(256, 2)
void gemm128(const float* __restrict__ A, const float* __restrict__ B,
             const float* __restrict__ bias,
             const float* __restrict__ add1, const float* __restrict__ add2,
             const float* __restrict__ qsp,
             float* __restrict__ C,
             int M, int N, int K,
             long sA, long sB, long sBias, long sC,
             float alpha, float beta, float c1, float c2, int do_gelu)
{
    __shared__ __align__(16) float As[8][128];
    __shared__ __align__(16) float Bs[8][128];

    int bz = blockIdx.z;
    A += (long)bz * sA;
    B += (long)bz * sB;
    C += (long)bz * sC;
    if (bias) bias += (long)bz * sBias;

    const int n0 = blockIdx.x * 128;
    const int m0 = blockIdx.y * 128;

    const int tid = threadIdx.x;
    const int tx = tid & 15, ty = tid >> 4;

    const int lrow = tid >> 1;          // 0..127
    const int lk4  = (tid & 1) * 4;     // 0 or 4
    const float* Ag = A + (long)(m0 + lrow) * K + lk4;
    const float* Bg = B + (long)(n0 + lrow) * K + lk4;

    unsigned long long acc[8][4];
#pragma unroll
    for (int i = 0; i < 8; i++)
#pragma unroll
        for (int j = 0; j < 4; j++) acc[i][j] = 0ULL;

    for (int k0 = 0; k0 < K; k0 += 8) {
        float4 av = *(const float4*)(Ag + k0);
        float4 bv = *(const float4*)(Bg + k0);
        __syncthreads();
        As[lk4+0][lrow] = av.x; As[lk4+1][lrow] = av.y;
        As[lk4+2][lrow] = av.z; As[lk4+3][lrow] = av.w;
        Bs[lk4+0][lrow] = bv.x; Bs[lk4+1][lrow] = bv.y;
        Bs[lk4+2][lrow] = bv.z; Bs[lk4+3][lrow] = bv.w;
        __syncthreads();
#pragma unroll
        for (int kk = 0; kk < 8; kk++) {
            float4 a0 = *(const float4*)&As[kk][ty * 4];
            float4 a1 = *(const float4*)&As[kk][64 + ty * 4];
            ulonglong2 b01 = *(const ulonglong2*)&Bs[kk][tx * 4];
            ulonglong2 b23 = *(const ulonglong2*)&Bs[kk][64 + tx * 4];
            unsigned long long bb[4] = { b01.x, b01.y, b23.x, b23.y };
            float aa[8] = { a0.x, a0.y, a0.z, a0.w, a1.x, a1.y, a1.z, a1.w };
#pragma unroll
            for (int i = 0; i < 8; i++) {
                unsigned long long a2 = bcast2(aa[i]);
#pragma unroll
                for (int j = 0; j < 4; j++) fma2(acc[i][j], a2, bb[j]);
            }
        }
    }

    float cc1 = c1, cc2 = c2;
    if (qsp) { float q = *qsp; cc1 = 1.0f - q; cc2 = q; }

#pragma unroll
    for (int i = 0; i < 8; i++) {
        int row = m0 + ((i < 4) ? (ty * 4 + i) : (64 + ty * 4 + (i - 4)));
#pragma unroll
        for (int j = 0; j < 4; j++) {
            int col = n0 + ((j < 2) ? (tx * 4 + j * 2) : (64 + tx * 4 + (j - 2) * 2));
            float2 p = unpack2(acc[i][j]);
            float v0 = alpha * p.x, v1 = alpha * p.y;
            if (bias) { v0 += beta * bias[col]; v1 += beta * bias[col + 1]; }
            if (do_gelu) {
                v0 = 0.5f * v0 * (1.0f + erff(v0 * 0.7071067811865475f));
                v1 = 0.5f * v1 * (1.0f + erff(v1 * 0.7071067811865475f));
            }
            long idx = (long)row * N + col;
            if (add1) { v0 += cc1 * add1[idx]; v1 += cc1 * add1[idx + 1]; }
            if (add2) { v0 += cc2 * add2[idx]; v1 += cc2 * add2[idx + 1]; }
            C[idx] = v0; C[idx + 1] = v1;
        }
    }
}

// ---------------- embedding gather ----------------
__global__ __launch_bounds__(256)
void embed_kernel(const int* __restrict__ src, const float* __restrict__ W,
                  float* __restrict__ emb)
{
    int t = blockIdx.x, tid = threadIdx.x;
    long row = (long)src[t] * DIM;
#pragma unroll
    for (int k = 0; k < 3; k++)
        emb[(long)t * DIM + tid + k * 256] = W[row + tid + k * 256];
}

// ---------------- attention: scores = scale * Q K^T (per head, 64x64 tiles) ----
__global__ __launch_bounds__(256)
void attn_scores(const float* __restrict__ qkv, float* __restrict__ scores)
{
    __shared__ __align__(16) float Qs[64][64];   // [hd][i]
    __shared__ __align__(16) float Ks[64][64];   // [hd][j]
    int bh = blockIdx.z;
    int b = bh / NH, h = bh % NH;
    int i0 = blockIdx.y * 64;
    int j0 = blockIdx.x * 64;
    int tid = threadIdx.x;
    int tx = tid & 15, ty = tid >> 4;

#pragma unroll
    for (int rep = 0; rep < 4; rep++) {
        int r  = rep * 16 + (tid >> 4);
        int c4 = (tid & 15) * 4;
        float4 q = *(const float4*)&qkv[((long)(b * SEQ + i0 + r)) * (3 * DIM) + h * HD + c4];
        float4 k = *(const float4*)&qkv[((long)(b * SEQ + j0 + r)) * (3 * DIM) + DIM + h * HD + c4];
        Qs[c4+0][r] = q.x; Qs[c4+1][r] = q.y; Qs[c4+2][r] = q.z; Qs[c4+3][r] = q.w;
        Ks[c4+0][r] = k.x; Ks[c4+1][r] = k.y; Ks[c4+2][r] = k.z; Ks[c4+3][r] = k.w;
    }
    __syncthreads();

    float acc[4][4] = {};
#pragma unroll 8
    for (int kk = 0; kk < 64; kk++) {
        float4 qa = *(const float4*)&Qs[kk][ty * 4];
        float4 kb = *(const float4*)&Ks[kk][tx * 4];
        float qr[4] = { qa.x, qa.y, qa.z, qa.w };
        float kr[4] = { kb.x, kb.y, kb.z, kb.w };
#pragma unroll
        for (int i = 0; i < 4; i++)
#pragma unroll
            for (int j = 0; j < 4; j++) acc[i][j] = fmaf(qr[i], kr[j], acc[i][j]);
    }
    const float scale = 0.125f;  // 1/sqrt(64)
    long base = (long)bh * SEQ * SEQ;
#pragma unroll
    for (int i = 0; i < 4; i++)
#pragma unroll
        for (int j = 0; j < 4; j++)
            scores[base + (long)(i0 + ty * 4 + i) * SEQ + j0 + tx * 4 + j] = acc[i][j] * scale;
}

// ---------------- row softmax over 512 ----------------
__global__ __launch_bounds__(256)
void softmax512(float* __restrict__ s)
{
    long base = (long)blockIdx.x * SEQ;
    int tid = threadIdx.x;
    float v0 = s[base + tid], v1 = s[base + 256 + tid];
    __shared__ float red[256];
    red[tid] = fmaxf(v0, v1);
    __syncthreads();
    for (int o = 128; o > 0; o >>= 1) { if (tid < o) red[tid] = fmaxf(red[tid], red[tid + o]); __syncthreads(); }
    float m = red[0];
    __syncthreads();
    float e0 = expf(v0 - m), e1 = expf(v1 - m);
    red[tid] = e0 + e1;
    __syncthreads();
    for (int o = 128; o > 0; o >>= 1) { if (tid < o) red[tid] += red[tid + o]; __syncthreads(); }
    float inv = 1.0f / red[0];
    s[base + tid] = e0 * inv;
    s[base + 256 + tid] = e1 * inv;
}

// ---------------- attention: O = P V (per head) ----------------
__global__ __launch_bounds__(256)
void attn_av(const float* __restrict__ qkv, const float* __restrict__ scores,
             float* __restrict__ attn)
{
    __shared__ __align__(16) float Ps[32][64];   // [j][i]
    __shared__ __align__(16) float Vs[32][64];   // [j][d]
    int bh = blockIdx.z;
    int b = bh / NH, h = bh % NH;
    int i0 = blockIdx.x * 64;
    int tid = threadIdx.x;
    int tx = tid & 15, ty = tid >> 4;
    long sbase = (long)bh * SEQ * SEQ;

    float acc[4][4] = {};
    for (int j0 = 0; j0 < SEQ; j0 += 32) {
        __syncthreads();
#pragma unroll
        for (int rep = 0; rep < 2; rep++) {
            int idx = rep * 256 + tid;
            int r  = idx >> 3;          // i  0..63
            int c4 = (idx & 7) * 4;     // j  0..28
            float4 p = *(const float4*)&scores[sbase + (long)(i0 + r) * SEQ + j0 + c4];
            Ps[c4+0][r] = p.x; Ps[c4+1][r] = p.y; Ps[c4+2][r] = p.z; Ps[c4+3][r] = p.w;
        }
#pragma unroll
        for (int rep = 0; rep < 2; rep++) {
            int idx = rep * 256 + tid;
            int r  = idx >> 4;          // j  0..31
            int c4 = (idx & 15) * 4;    // d
            float4 v = *(const float4*)&qkv[((long)(b * SEQ + j0 + r)) * (3 * DIM) + 2 * DIM + h * HD + c4];
            *(float4*)&Vs[r][c4] = v;
        }
        __syncthreads();
#pragma unroll
        for (int kk = 0; kk < 32; kk++) {
            float4 pa = *(const float4*)&Ps[kk][ty * 4];
            float4 vb = *(const float4*)&Vs[kk][tx * 4];
            float pr[4] = { pa.x, pa.y, pa.z, pa.w };
            float vr[4] = { vb.x, vb.y, vb.z, vb.w };
#pragma unroll
            for (int i = 0; i < 4; i++)
#pragma unroll
                for (int j = 0; j < 4; j++) acc[i][j] = fmaf(pr[i], vr[j], acc[i][j]);
        }
    }
#pragma unroll
    for (int i = 0; i < 4; i++)
#pragma unroll
        for (int j = 0; j < 4; j++)
            attn[((long)(b * SEQ + i0 + ty * 4 + i)) * DIM + h * HD + tx * 4 + j] = acc[i][j];
}

// ---------------- gating: softmax(gate)*(1+0.1*sigmoid(qgate)), renormalized ---
__global__ __launch_bounds__(256)
void gates_kernel(const float* __restrict__ x, const float* __restrict__ gw,
                  const float* __restrict__ gb, const float* __restrict__ qw,
                  const float* __restrict__ qb, float* __restrict__ gates)
{
    int t = blockIdx.x, tid = threadIdx.x;
    __shared__ float xs[DIM];
    __shared__ float lg[NE], lq[NE];
#pragma unroll
    for (int k = 0; k < 3; k++) xs[tid + k * 256] = x[(long)t * DIM + tid + k * 256];
    __syncthreads();
    int w = tid >> 5, lane = tid & 31;   // 8 warps, warp w -> expert w
    float ag = 0.f, aq = 0.f;
    for (int d = lane; d < DIM; d += 32) {
        float xv = xs[d];
        ag = fmaf(xv, gw[w * DIM + d], ag);
        aq = fmaf(xv, qw[w * DIM + d], aq);
    }
    for (int o = 16; o > 0; o >>= 1) {
        ag += __shfl_down_sync(0xffffffffu, ag, o);
        aq += __shfl_down_sync(0xffffffffu, aq, o);
    }
    if (lane == 0) { lg[w] = ag + gb[w]; lq[w] = aq + qb[w]; }
    __syncthreads();
    if (tid == 0) {
        float m = lg[0];
        for (int e = 1; e < NE; e++) m = fmaxf(m, lg[e]);
        float ex[NE], s = 0.f;
        for (int e = 0; e < NE; e++) { ex[e] = expf(lg[e] - m); s += ex[e]; }
        float gg[NE], tot = 0.f;
        for (int e = 0; e < NE; e++) {
            float sm = ex[e] / s;
            float sg = 1.0f / (1.0f + expf(-lq[e]));
            gg[e] = sm * (1.0f + 0.1f * sg);
            tot += gg[e];
        }
        for (int e = 0; e < NE; e++) gates[t * NE + e] = gg[e] / tot;
    }
}

// ---------------- MoE combine + residual + LayerNorm (in-place on x) ----------
__global__ __launch_bounds__(256)
void moe_ln(const float* __restrict__ eo, const float* __restrict__ gates,
            float* __restrict__ x, const float* __restrict__ lng,
            const float* __restrict__ lnb)
{
    int t = blockIdx.x, tid = threadIdx.x;
    __shared__ float gs[NE];
    __shared__ float red[256];
    if (tid < NE) gs[tid] = gates[t * NE + tid];
    __syncthreads();
    float y[3];
    float s = 0.f;
#pragma unroll
    for (int k = 0; k < 3; k++) {
        int d = tid + k * 256;
        float m = 0.f;
#pragma unroll
        for (int e = 0; e < NE; e++)
            m = fmaf(gs[e], eo[((long)e * T_TOK + t) * DIM + d], m);
        float v = x[(long)t * DIM + d] + m;
        y[k] = v; s += v;
    }
    red[tid] = s; __syncthreads();
    for (int o = 128; o > 0; o >>= 1) { if (tid < o) red[tid] += red[tid + o]; __syncthreads(); }
    float mean = red[0] * (1.0f / DIM);
    __syncthreads();
    float s2 = 0.f;
#pragma unroll
    for (int k = 0; k < 3; k++) { float d0 = y[k] - mean; s2 += d0 * d0; }
    red[tid] = s2; __syncthreads();
    for (int o = 128; o > 0; o >>= 1) { if (tid < o) red[tid] += red[tid + o]; __syncthreads(); }
    float inv = rsqrtf(red[0] * (1.0f / DIM) + 1e-5f);
#pragma unroll
    for (int k = 0; k < 3; k++) {
        int d = tid + k * 256;
        x[(long)t * DIM + d] = (y[k] - mean) * inv * lng[d] + lnb[d];
    }
}

// ---------------- host driver ----------------
static void launch_gemm(const float* A, const float* B, const float* bias,
                        const float* add1, const float* add2, const float* qs,
                        float* C, int M, int N, int K,
                        long sA, long sB, long sBias, long sC, int batch,
                        float alpha, float beta, float c1, float c2, int gelu)
{
    dim3 grid(N / 128, M / 128, batch);
    gemm128<<<grid, 256>>>(A, B, bias, add1, add2, qs, C, M, N, K,
                           sA, sB, sBias, sC, alpha, beta, c1, c2, gelu);
}

extern "C" void kernel_launch(void* const* d_in, const int* in_sizes, int n_in,
                              void* d_out, int out_size)
{
    const int*   src       = (const int*)  d_in[0];
    const float* qs        = (const float*)d_in[1];   // quantum_state [1] (device)
    const float* noise     = (const float*)d_in[2];
    const float* embed_W   = (const float*)d_in[3];
    const float* qproj_w   = (const float*)d_in[4];
    const float* qproj_b   = (const float*)d_in[5];
    const float* pos_w     = (const float*)d_in[6];
    const float* pos_b     = (const float*)d_in[7];
    const float* in_proj_w = (const float*)d_in[8];
    const float* in_proj_b = (const float*)d_in[9];
    const float* out_proj_w= (const float*)d_in[10];
    const float* out_proj_b= (const float*)d_in[11];
    const float* ent_w     = (const float*)d_in[12];
    const float* ent_b     = (const float*)d_in[13];
    const float* gate_w    = (const float*)d_in[14];
    const float* gate_b    = (const float*)d_in[15];
    const float* qgate_w   = (const float*)d_in[16];
    const float* qgate_b   = (const float*)d_in[17];
    const float* e_w1      = (const float*)d_in[18];
    const float* e_b1      = (const float*)d_in[19];
    const float* e_w2      = (const float*)d_in[20];
    const float* e_b2      = (const float*)d_in[21];
    const float* ln_g      = (const float*)d_in[22];
    const float* ln_b      = (const float*)d_in[23];
    const float* fc_w      = (const float*)d_in[24];
    const float* fc_b      = (const float*)d_in[25];
    float* out = (float*)d_out;

    float *x, *emb, *tmp, *attn, *qkv, *scores, *hbuf, *eo, *gates;
    cudaGetSymbolAddress((void**)&x,      g_x);
    cudaGetSymbolAddress((void**)&emb,    g_emb);
    cudaGetSymbolAddress((void**)&tmp,    g_tmp);
    cudaGetSymbolAddress((void**)&attn,   g_attn);
    cudaGetSymbolAddress((void**)&qkv,    g_qkv);
    cudaGetSymbolAddress((void**)&scores, g_scores);
    cudaGetSymbolAddress((void**)&hbuf,   g_h);
    cudaGetSymbolAddress((void**)&eo,     g_eo);
    cudaGetSymbolAddress((void**)&gates,  g_gates);

    // --- prologue: quantum embedding + positional mix ---
    embed_kernel<<<T_TOK, 256>>>(src, embed_W, emb);
    // tmp = emb @ qproj^T + qproj_b
    launch_gemm(emb, qproj_w, qproj_b, nullptr, nullptr, nullptr, tmp,
                T_TOK, DIM, DIM, 0, 0, 0, 0, 1, 1.f, 1.f, 0.f, 0.f, 0);
    // x = 0.01*(noise @ pos^T) + pos_b + (1-qs)*emb + qs*tmp
    launch_gemm(noise, pos_w, pos_b, emb, tmp, qs, x,
                T_TOK, DIM, DIM, 0, 0, 0, 0, 1, 0.01f, 1.f, 0.f, 0.f, 0);

    for (int l = 0; l < NL; l++) {
        // qkv = x @ in_proj^T + b
        launch_gemm(x, in_proj_w + (long)l * 3 * DIM * DIM, in_proj_b + l * 3 * DIM,
                    nullptr, nullptr, nullptr, qkv,
                    T_TOK, 3 * DIM, DIM, 0, 0, 0, 0, 1, 1.f, 1.f, 0.f, 0.f, 0);
        attn_scores<<<dim3(SEQ / 64, SEQ / 64, BAT * NH), 256>>>(qkv, scores);
        softmax512<<<BAT * NH * SEQ, 256>>>(scores);
        attn_av<<<dim3(SEQ / 64, 1, BAT * NH), 256>>>(qkv, scores, attn);
        // tmp = attn @ out_proj^T + b
        launch_gemm(attn, out_proj_w + (long)l * DIM * DIM, out_proj_b + l * DIM,
                    nullptr, nullptr, nullptr, tmp,
                    T_TOK, DIM, DIM, 0, 0, 0, 0, 1, 1.f, 1.f, 0.f, 0.f, 0);
        // x = x + tmp + 0.1*(tmp @ ent^T + ent_b)
        launch_gemm(tmp, ent_w + (long)l * DIM * DIM, ent_b + l * DIM,
                    x, tmp, nullptr, x,
                    T_TOK, DIM, DIM, 0, 0, 0, 0, 1, 0.1f, 0.1f, 1.f, 1.f, 0);
        // gates
        gates_kernel<<<T_TOK, 256>>>(x, gate_w + (long)l * NE * DIM, gate_b + l * NE,
                                     qgate_w + (long)l * NE * DIM, qgate_b + l * NE, gates);
        // h[e] = gelu(x @ e_w1[l,e]^T + e_b1[l,e])   (batched over experts)
        launch_gemm(x, e_w1 + (long)l * NE * FF * DIM, e_b1 + (long)l * NE * FF,
                    nullptr, nullptr, nullptr, hbuf,
                    T_TOK, FF, DIM, 0, (long)FF * DIM, FF, (long)T_TOK * FF, NE,
                    1.f, 1.f, 0.f, 0.f, 1);
        // eo[e] = h[e] @ e_w2[l,e]^T + e_b2[l,e]
        launch_gemm(hbuf, e_w2 + (long)l * NE * DIM * FF, e_b2 + (long)l * NE * DIM,
                    nullptr, nullptr, nullptr, eo,
                    T_TOK, DIM, FF, (long)T_TOK * FF, (long)DIM * FF, DIM, (long)T_TOK * DIM, NE,
                    1.f, 1.f, 0.f, 0.f, 0);
        // x = LN(x + sum_e gates[t,e]*eo[e,t,:])
        moe_ln<<<T_TOK, 256>>>(eo, gates, x, ln_g + l * DIM, ln_b + l * DIM);
    }

    // logits = x @ fc_w^T + fc_b
    launch_gemm(x, fc_w, fc_b, nullptr, nullptr, nullptr, out,
                T_TOK, VOC, DIM, 0, 0, 0, 0, 1, 1.f, 1.f, 0.f, 0.f, 0);
}